// round 3
// baseline (speedup 1.0000x reference)
#include <cuda_runtime.h>
#include <cstdint>

#define BB 32
#define SS 2048
#define EE 128
#define HH 8
#define DD 16
#define HD 128
#define KTOT 132
#define CACHE 256
#define WINDOW 128
#define SINKS 4

// d_out layout: [output (B*S*HD)] [new_k (B*H*128*16)] [new_v (B*H*128*16)]
#define OUT_ELEMS (BB * SS * HD)            // 8388608
#define KOFF OUT_ELEMS                      // 8388608
#define VOFF (KOFF + BB * HH * WINDOW * DD) // 8912896

// ---------------- scratch (device globals; no allocation APIs) ----------------
__device__ float    g_q[(size_t)BB * SS * HD];        // 33.5 MB, layout (b,s,h*d), pre-scaled by 0.25
__device__ float    g_ao[(size_t)BB * SS * HD];       // 33.5 MB, layout (b,s,h*d)
__device__ unsigned g_wq[4][32 * 128];                // packed ternary weights (q,k,v,o)
__device__ float    g_ws[4];                          // w_scale per weight
__device__ unsigned g_amax_x;
__device__ unsigned g_amax_o;

// ---------------- f32x2 packed-math helpers (sm_103a) ----------------
__device__ __forceinline__ unsigned long long f2_mul(unsigned long long a, unsigned long long b) {
    unsigned long long d;
    asm("mul.rn.f32x2 %0,%1,%2;" : "=l"(d) : "l"(a), "l"(b));
    return d;
}
__device__ __forceinline__ unsigned long long f2_fma(unsigned long long a, unsigned long long b,
                                                     unsigned long long c) {
    unsigned long long d;
    asm("fma.rn.f32x2 %0,%1,%2,%3;" : "=l"(d) : "l"(a), "l"(b), "l"(c));
    return d;
}
__device__ __forceinline__ unsigned long long f2_add(unsigned long long a, unsigned long long b) {
    unsigned long long d;
    asm("add.rn.f32x2 %0,%1,%2;" : "=l"(d) : "l"(a), "l"(b));
    return d;
}
__device__ __forceinline__ unsigned long long f2_pack(float lo, float hi) {
    unsigned long long d;
    asm("mov.b64 %0,{%1,%2};" : "=l"(d) : "f"(lo), "f"(hi));
    return d;
}
__device__ __forceinline__ float2 f2_unpack(unsigned long long v) {
    float2 r;
    asm("mov.b64 {%0,%1},%2;" : "=f"(r.x), "=f"(r.y) : "l"(v));
    return r;
}

// ---------------- helpers ----------------
__device__ __forceinline__ unsigned quant4(float4 v, float is_inv) {
    int a = __float2int_rn(fminf(fmaxf(v.x * is_inv, -128.f), 127.f));
    int b = __float2int_rn(fminf(fmaxf(v.y * is_inv, -128.f), 127.f));
    int c = __float2int_rn(fminf(fmaxf(v.z * is_inv, -128.f), 127.f));
    int d = __float2int_rn(fminf(fmaxf(v.w * is_inv, -128.f), 127.f));
    return (unsigned)(a & 0xFF) | ((unsigned)(b & 0xFF) << 8) |
           ((unsigned)(c & 0xFF) << 16) | ((unsigned)(d & 0xFF) << 24);
}

// ---------------- kernel 1: w_scale + ternarize + pack (4 blocks) + init -----
__global__ __launch_bounds__(256) void k_prep(const float* qw, const float* kw,
                                              const float* vw, const float* ow) {
    int bw = blockIdx.x;
    if (bw == 0 && threadIdx.x == 0) { g_amax_x = 0u; g_amax_o = 0u; }
    const float* w = (bw == 0) ? qw : (bw == 1) ? kw : (bw == 2) ? vw : ow;
    __shared__ float red[256];
    __shared__ float ws_s;
    int t = threadIdx.x;
    float s = 0.f;
    for (int i = t; i < 16384; i += 256) s += fabsf(w[i]);
    red[t] = s;
    __syncthreads();
    for (int o = 128; o > 0; o >>= 1) {
        if (t < o) red[t] += red[t + o];
        __syncthreads();
    }
    if (t == 0) { ws_s = red[0] / 16384.0f; g_ws[bw] = ws_s; }
    __syncthreads();
    float thr = 0.5f * ws_s;
    int c = t >> 1, half = t & 1;
    for (int i = 0; i < 16; i++) {
        int kk = half * 16 + i;
        float4 wv = *(const float4*)(w + c * 128 + kk * 4);
        int t0 = (fabsf(wv.x) > thr) ? (wv.x > 0.f ? 1 : -1) : 0;
        int t1 = (fabsf(wv.y) > thr) ? (wv.y > 0.f ? 1 : -1) : 0;
        int t2 = (fabsf(wv.z) > thr) ? (wv.z > 0.f ? 1 : -1) : 0;
        int t3 = (fabsf(wv.w) > thr) ? (wv.w > 0.f ? 1 : -1) : 0;
        unsigned p = (unsigned)(t0 & 0xFF) | ((unsigned)(t1 & 0xFF) << 8) |
                     ((unsigned)(t2 & 0xFF) << 16) | ((unsigned)(t3 & 0xFF) << 24);
        g_wq[bw][kk * 128 + c] = p;
    }
}

// ---------------- kernel 2: abs-max over x ----------------
__global__ __launch_bounds__(256) void k_amax(const float* x, int n4) {
    int idx = blockIdx.x * blockDim.x + threadIdx.x;
    int stride = gridDim.x * blockDim.x;
    float m = 0.f;
    const float4* x4 = (const float4*)x;
    for (int i = idx; i < n4; i += stride) {
        float4 v = x4[i];
        m = fmaxf(m, fmaxf(fmaxf(fabsf(v.x), fabsf(v.y)), fmaxf(fabsf(v.z), fabsf(v.w))));
    }
    for (int o = 16; o; o >>= 1) m = fmaxf(m, __shfl_xor_sync(0xFFFFFFFFu, m, o));
    if ((threadIdx.x & 31) == 0) atomicMax(&g_amax_x, __float_as_uint(m));
}

// ---------------- shared GEMM core: 32 rows x 128 cols, dp4a ----------------
// 256 threads. warp w owns rows 4w..4w+3; lane owns cols 4*lane..4*lane+3
#define DP(a, b, c) c = __dp4a((int)(a), (int)(b), c)

__device__ __forceinline__ void bitgemm_core(const float* xbase, const unsigned* wq_g,
                                             float is_inv, unsigned* xq_s, unsigned* wq_s,
                                             int (&acc)[4][4]) {
    int t = threadIdx.x;
    {
        int row = t >> 3, seg = t & 7;
        const float4* src = (const float4*)(xbase + row * 128 + seg * 16);
        uint4 pk;
        pk.x = quant4(src[0], is_inv);
        pk.y = quant4(src[1], is_inv);
        pk.z = quant4(src[2], is_inv);
        pk.w = quant4(src[3], is_inv);
        *(uint4*)(xq_s + row * 32 + seg * 4) = pk;
    }
    {
        const uint4* src = (const uint4*)wq_g;
        uint4* dst = (uint4*)wq_s;
#pragma unroll
        for (int i = 0; i < 4; i++) dst[t + i * 256] = src[t + i * 256];
    }
    __syncthreads();
    int warp = t >> 5, lane = t & 31;
#pragma unroll
    for (int rr = 0; rr < 4; rr++)
#pragma unroll
        for (int cc = 0; cc < 4; cc++) acc[rr][cc] = 0;
    const uint4* x4 = (const uint4*)xq_s;  // [row*8 + kk/4]
    const uint4* w4 = (const uint4*)wq_s;  // [kk*32 + lane] = cols 4l..4l+3 at word kk
#pragma unroll
    for (int kk = 0; kk < 32; kk += 4) {
        uint4 xr0 = x4[(warp * 4 + 0) * 8 + (kk >> 2)];
        uint4 xr1 = x4[(warp * 4 + 1) * 8 + (kk >> 2)];
        uint4 xr2 = x4[(warp * 4 + 2) * 8 + (kk >> 2)];
        uint4 xr3 = x4[(warp * 4 + 3) * 8 + (kk >> 2)];
        uint4 w0 = w4[(kk + 0) * 32 + lane];
        uint4 w1 = w4[(kk + 1) * 32 + lane];
        uint4 w2 = w4[(kk + 2) * 32 + lane];
        uint4 w3 = w4[(kk + 3) * 32 + lane];
        DP(xr0.x, w0.x, acc[0][0]); DP(xr0.y, w1.x, acc[0][0]); DP(xr0.z, w2.x, acc[0][0]); DP(xr0.w, w3.x, acc[0][0]);
        DP(xr0.x, w0.y, acc[0][1]); DP(xr0.y, w1.y, acc[0][1]); DP(xr0.z, w2.y, acc[0][1]); DP(xr0.w, w3.y, acc[0][1]);
        DP(xr0.x, w0.z, acc[0][2]); DP(xr0.y, w1.z, acc[0][2]); DP(xr0.z, w2.z, acc[0][2]); DP(xr0.w, w3.z, acc[0][2]);
        DP(xr0.x, w0.w, acc[0][3]); DP(xr0.y, w1.w, acc[0][3]); DP(xr0.z, w2.w, acc[0][3]); DP(xr0.w, w3.w, acc[0][3]);
        DP(xr1.x, w0.x, acc[1][0]); DP(xr1.y, w1.x, acc[1][0]); DP(xr1.z, w2.x, acc[1][0]); DP(xr1.w, w3.x, acc[1][0]);
        DP(xr1.x, w0.y, acc[1][1]); DP(xr1.y, w1.y, acc[1][1]); DP(xr1.z, w2.y, acc[1][1]); DP(xr1.w, w3.y, acc[1][1]);
        DP(xr1.x, w0.z, acc[1][2]); DP(xr1.y, w1.z, acc[1][2]); DP(xr1.z, w2.z, acc[1][2]); DP(xr1.w, w3.z, acc[1][2]);
        DP(xr1.x, w0.w, acc[1][3]); DP(xr1.y, w1.w, acc[1][3]); DP(xr1.z, w2.w, acc[1][3]); DP(xr1.w, w3.w, acc[1][3]);
        DP(xr2.x, w0.x, acc[2][0]); DP(xr2.y, w1.x, acc[2][0]); DP(xr2.z, w2.x, acc[2][0]); DP(xr2.w, w3.x, acc[2][0]);
        DP(xr2.x, w0.y, acc[2][1]); DP(xr2.y, w1.y, acc[2][1]); DP(xr2.z, w2.y, acc[2][1]); DP(xr2.w, w3.y, acc[2][1]);
        DP(xr2.x, w0.z, acc[2][2]); DP(xr2.y, w1.z, acc[2][2]); DP(xr2.z, w2.z, acc[2][2]); DP(xr2.w, w3.z, acc[2][2]);
        DP(xr2.x, w0.w, acc[2][3]); DP(xr2.y, w1.w, acc[2][3]); DP(xr2.z, w2.w, acc[2][3]); DP(xr2.w, w3.w, acc[2][3]);
        DP(xr3.x, w0.x, acc[3][0]); DP(xr3.y, w1.x, acc[3][0]); DP(xr3.z, w2.x, acc[3][0]); DP(xr3.w, w3.x, acc[3][0]);
        DP(xr3.x, w0.y, acc[3][1]); DP(xr3.y, w1.y, acc[3][1]); DP(xr3.z, w2.y, acc[3][1]); DP(xr3.w, w3.y, acc[3][1]);
        DP(xr3.x, w0.z, acc[3][2]); DP(xr3.y, w1.z, acc[3][2]); DP(xr3.z, w2.z, acc[3][2]); DP(xr3.w, w3.z, acc[3][2]);
        DP(xr3.x, w0.w, acc[3][3]); DP(xr3.y, w1.w, acc[3][3]); DP(xr3.z, w2.w, acc[3][3]); DP(xr3.w, w3.w, acc[3][3]);
    }
}

// ---------------- kernel 3: Q + K/V projections in one launch ----------------
// blocks [0, 2048): Q rows; [2048, 2176): K rows; [2176, 2304): V rows
__global__ __launch_bounds__(256) void k_proj(const float* x, const float* qb,
                                              const float* kb, const float* vb,
                                              float* out) {
    __shared__ unsigned xq_s[32 * 32];
    __shared__ unsigned wq_s[32 * 128];
    int blk = blockIdx.x;
    float amax = __uint_as_float(g_amax_x);
    float is_inv = __fdiv_rn(127.0f, amax);
    float is = amax * (1.0f / 127.0f);
    int warp = threadIdx.x >> 5, lane = threadIdx.x & 31;
    int c0 = lane * 4;
    int acc[4][4];

    if (blk < 2048) {  // ---- Q ---- (pre-scaled by softmax 1/sqrt(D) = 0.25)
        int row0 = blk * 32;
        float sc = g_ws[0] * is;
        bitgemm_core(x + (size_t)row0 * 128, g_wq[0], is_inv, xq_s, wq_s, acc);
        float4 bias = *(const float4*)(qb + c0);
#pragma unroll
        for (int rr = 0; rr < 4; rr++) {
            int r = row0 + warp * 4 + rr;
            float4 o;
            o.x = ((float)acc[rr][0] * sc + bias.x) * 0.25f;
            o.y = ((float)acc[rr][1] * sc + bias.y) * 0.25f;
            o.z = ((float)acc[rr][2] * sc + bias.z) * 0.25f;
            o.w = ((float)acc[rr][3] * sc + bias.w) * 0.25f;
            *(float4*)(g_q + (size_t)r * 128 + c0) = o;
        }
    } else {  // ---- K or V, last 128 tokens of each batch ----
        int which = (blk >= 2176) ? 1 : 0;
        int row0 = (blk - (which ? 2176 : 2048)) * 32;  // r in [0,4096)
        int b = row0 >> 7, i0 = row0 & 127;
        const float* xbase = x + (((size_t)b * SS) + (SS - WINDOW) + i0) * EE;
        float sc = g_ws[1 + which] * is;
        const float* bias_p = which ? vb : kb;
        size_t base = which ? (size_t)VOFF : (size_t)KOFF;
        bitgemm_core(xbase, g_wq[1 + which], is_inv, xq_s, wq_s, acc);
        float4 bias = *(const float4*)(bias_p + c0);
        int h = c0 >> 4, d0 = c0 & 15;
#pragma unroll
        for (int rr = 0; rr < 4; rr++) {
            int r = row0 + warp * 4 + rr;
            int b2 = r >> 7, ii = r & 127;
            float4 o;
            o.x = (float)acc[rr][0] * sc + bias.x;
            o.y = (float)acc[rr][1] * sc + bias.y;
            o.z = (float)acc[rr][2] * sc + bias.z;
            o.w = (float)acc[rr][3] * sc + bias.w;
            *(float4*)(out + base + (((size_t)(b2 * HH + h)) * WINDOW + ii) * DD + d0) = o;
        }
    }
}

// ---------------- attention inner machinery ----------------
#define NEG_INF __int_as_float(0xff800000)

struct AttState {
    unsigned long long q[8];
    unsigned long long a[8];
    float m, l;
};

__device__ __forceinline__ void att_load_q(AttState& st, const float* qptr) {
    const ulonglong2* qp = (const ulonglong2*)qptr;
    ulonglong2 q01 = qp[0], q23 = qp[1], q45 = qp[2], q67 = qp[3];
    st.q[0] = q01.x; st.q[1] = q01.y; st.q[2] = q23.x; st.q[3] = q23.y;
    st.q[4] = q45.x; st.q[5] = q45.y; st.q[6] = q67.x; st.q[7] = q67.y;
#pragma unroll
    for (int i = 0; i < 8; i++) st.a[i] = 0ull;
    st.m = NEG_INF;
    st.l = 0.f;
}

__device__ __forceinline__ float att_score(const AttState& st,
                                           const ulonglong2& kA, const ulonglong2& kB,
                                           const ulonglong2& kC, const ulonglong2& kD) {
    unsigned long long d0 = f2_mul(st.q[0], kA.x);
    unsigned long long d1 = f2_mul(st.q[1], kA.y);
    d0 = f2_fma(st.q[2], kB.x, d0);
    d1 = f2_fma(st.q[3], kB.y, d1);
    d0 = f2_fma(st.q[4], kC.x, d0);
    d1 = f2_fma(st.q[5], kC.y, d1);
    d0 = f2_fma(st.q[6], kD.x, d0);
    d1 = f2_fma(st.q[7], kD.y, d1);
    float2 ds = f2_unpack(f2_add(d0, d1));
    return ds.x + ds.y;
}

__device__ __forceinline__ void att_update(AttState& st, float sc,
                                           const ulonglong2& vA, const ulonglong2& vB,
                                           const ulonglong2& vC, const ulonglong2& vD) {
    if (sc > st.m) {
        float r = __expf(st.m - sc);  // first time: exp(-inf)=0
        unsigned long long r2 = f2_pack(r, r);
        st.l = fmaf(st.l, r, 1.0f);
        st.a[0] = f2_fma(st.a[0], r2, vA.x);
        st.a[1] = f2_fma(st.a[1], r2, vA.y);
        st.a[2] = f2_fma(st.a[2], r2, vB.x);
        st.a[3] = f2_fma(st.a[3], r2, vB.y);
        st.a[4] = f2_fma(st.a[4], r2, vC.x);
        st.a[5] = f2_fma(st.a[5], r2, vC.y);
        st.a[6] = f2_fma(st.a[6], r2, vD.x);
        st.a[7] = f2_fma(st.a[7], r2, vD.y);
        st.m = sc;
    } else {
        float p = __expf(sc - st.m);
        unsigned long long p2 = f2_pack(p, p);
        st.l += p;
        st.a[0] = f2_fma(p2, vA.x, st.a[0]);
        st.a[1] = f2_fma(p2, vA.y, st.a[1]);
        st.a[2] = f2_fma(p2, vB.x, st.a[2]);
        st.a[3] = f2_fma(p2, vB.y, st.a[3]);
        st.a[4] = f2_fma(p2, vC.x, st.a[4]);
        st.a[5] = f2_fma(p2, vC.y, st.a[5]);
        st.a[6] = f2_fma(p2, vD.x, st.a[6]);
        st.a[7] = f2_fma(p2, vD.y, st.a[7]);
    }
}

__device__ __forceinline__ float att_finish(AttState& st, float* optr) {
    float inv = 1.0f / st.l;
    unsigned long long inv2 = f2_pack(inv, inv);
    float mx = 0.f;
#pragma unroll
    for (int i = 0; i < 8; i++) {
        st.a[i] = f2_mul(st.a[i], inv2);
        float2 u = f2_unpack(st.a[i]);
        mx = fmaxf(mx, fmaxf(fabsf(u.x), fabsf(u.y)));
    }
    ulonglong2* op = (ulonglong2*)optr;
    op[0] = make_ulonglong2(st.a[0], st.a[1]);
    op[1] = make_ulonglong2(st.a[2], st.a[3]);
    op[2] = make_ulonglong2(st.a[4], st.a[5]);
    op[3] = make_ulonglong2(st.a[6], st.a[7]);
    return mx;
}

// ---------------- kernel 5: attention, 2 queries/thread, f32x2 ----------------
// grid: (SS/512, H, B), 256 threads. Thread t handles queries chunk*512+t and +256.
__global__ __launch_bounds__(256, 2) void k_attn(const float* cached_k, const float* cached_v,
                                                 const float* outbuf) {
    __shared__ __align__(16) float ks[KTOT * DD];
    __shared__ __align__(16) float vs[KTOT * DD];
    int b = blockIdx.z, h = blockIdx.y, chunk = blockIdx.x;
    int t = threadIdx.x;
    size_t bh = (size_t)(b * HH + h);
    {
        const float* knew = outbuf + KOFF + bh * WINDOW * DD;
        const float* vnew = outbuf + VOFF + bh * WINDOW * DD;
        const float* kc = cached_k + bh * CACHE * DD;
        const float* vc = cached_v + bh * CACHE * DD;
        for (int i = t; i < KTOT * DD; i += 256) {
            int j = i >> 4;
            ks[i] = (j < SINKS) ? kc[i] : knew[i - SINKS * DD];
            vs[i] = (j < SINKS) ? vc[i] : vnew[i - SINKS * DD];
        }
    }
    __syncthreads();

    int s0 = chunk * 512 + t;
    int s1 = s0 + 256;
    const float* qbase = g_q + ((size_t)b * SS) * HD + h * DD;
    AttState st0, st1;
    att_load_q(st0, qbase + (size_t)s0 * HD);
    att_load_q(st1, qbase + (size_t)s1 * HD);

    const ulonglong2* k2 = (const ulonglong2*)ks;
    const ulonglong2* v2 = (const ulonglong2*)vs;

    if (chunk != 0) {
        // full: both queries attend to all 132 keys
#pragma unroll 2
        for (int j = 0; j < KTOT; j++) {
            ulonglong2 kA = k2[j * 4 + 0], kB = k2[j * 4 + 1];
            ulonglong2 kC = k2[j * 4 + 2], kD = k2[j * 4 + 3];
            float sc0 = att_score(st0, kA, kB, kC, kD);
            float sc1 = att_score(st1, kA, kB, kC, kD);
            ulonglong2 vA = v2[j * 4 + 0], vB = v2[j * 4 + 1];
            ulonglong2 vC = v2[j * 4 + 2], vD = v2[j * 4 + 3];
            att_update(st0, sc0, vA, vB, vC, vD);
            att_update(st1, sc1, vA, vB, vC, vD);
        }
    } else {
        // chunk 0: query s0 = t in [0,255] may be causal-ragged; s1 >= 256 is full
        int jmax0 = min(s0, KTOT - 1);
        for (int j = 0; j < KTOT; j++) {
            ulonglong2 kA = k2[j * 4 + 0], kB = k2[j * 4 + 1];
            ulonglong2 kC = k2[j * 4 + 2], kD = k2[j * 4 + 3];
            float sc0 = att_score(st0, kA, kB, kC, kD);
            float sc1 = att_score(st1, kA, kB, kC, kD);
            sc0 = (j <= jmax0) ? sc0 : NEG_INF;  // masked => exp()=0 contribution
            ulonglong2 vA = v2[j * 4 + 0], vB = v2[j * 4 + 1];
            ulonglong2 vC = v2[j * 4 + 2], vD = v2[j * 4 + 3];
            att_update(st0, sc0, vA, vB, vC, vD);
            att_update(st1, sc1, vA, vB, vC, vD);
        }
    }

    float* aob = g_ao + ((size_t)b * SS) * HD + h * DD;
    float mx0 = att_finish(st0, aob + (size_t)s0 * HD);
    float mx1 = att_finish(st1, aob + (size_t)s1 * HD);
    float mx = fmaxf(mx0, mx1);
    for (int o = 16; o; o >>= 1) mx = fmaxf(mx, __shfl_xor_sync(0xFFFFFFFFu, mx, o));
    if ((t & 31) == 0) atomicMax(&g_amax_o, __float_as_uint(mx));
}

// ---------------- kernel 6: O projection ----------------
__global__ __launch_bounds__(256) void k_oproj(const float* ob, float* out) {
    __shared__ unsigned xq_s[32 * 32];
    __shared__ unsigned wq_s[32 * 128];
    int row0 = blockIdx.x * 32;
    float amax = __uint_as_float(g_amax_o);
    float is_inv = __fdiv_rn(127.0f, amax);
    float sc = g_ws[3] * (amax * (1.0f / 127.0f));
    int acc[4][4];
    bitgemm_core(g_ao + (size_t)row0 * 128, g_wq[3], is_inv, xq_s, wq_s, acc);
    int warp = threadIdx.x >> 5, lane = threadIdx.x & 31;
    int c0 = lane * 4;
    float4 bias = *(const float4*)(ob + c0);
#pragma unroll
    for (int rr = 0; rr < 4; rr++) {
        int r = row0 + warp * 4 + rr;
        float4 o;
        o.x = (float)acc[rr][0] * sc + bias.x;
        o.y = (float)acc[rr][1] * sc + bias.y;
        o.z = (float)acc[rr][2] * sc + bias.z;
        o.w = (float)acc[rr][3] * sc + bias.w;
        *(float4*)(out + (size_t)r * 128 + c0) = o;
    }
}

// ---------------- launcher ----------------
extern "C" void kernel_launch(void* const* d_in, const int* in_sizes, int n_in,
                              void* d_out, int out_size) {
    const float* x  = (const float*)d_in[0];
    const float* ck = (const float*)d_in[1];
    const float* cv = (const float*)d_in[2];
    const float* qb = (const float*)d_in[4];
    const float* kb = (const float*)d_in[6];
    const float* vb = (const float*)d_in[8];
    const float* ob = (const float*)d_in[10];
    const float* qw = (const float*)d_in[3];
    const float* kw = (const float*)d_in[5];
    const float* vw = (const float*)d_in[7];
    const float* ow = (const float*)d_in[9];
    float* out = (float*)d_out;

    k_prep<<<4, 256>>>(qw, kw, vw, ow);
    k_amax<<<1024, 256>>>(x, (BB * SS * EE) / 4);
    k_proj<<<2048 + 256, 256>>>(x, qb, kb, vb, out);
    k_attn<<<dim3(SS / 512, HH, BB), 256>>>(ck, cv, out);
    k_oproj<<<(BB * SS) / 32, 256>>>(ob, out);
}

// round 4
// speedup vs baseline: 1.3660x; 1.3660x over previous
#include <cuda_runtime.h>
#include <cstdint>

#define BB 32
#define SS 2048
#define EE 128
#define HH 8
#define DD 16
#define HD 128
#define KTOT 132
#define CACHE 256
#define WINDOW 128
#define SINKS 4

// d_out layout: [output (B*S*HD)] [new_k (B*H*128*16)] [new_v (B*H*128*16)]
#define OUT_ELEMS (BB * SS * HD)            // 8388608
#define KOFF OUT_ELEMS                      // 8388608
#define VOFF (KOFF + BB * HH * WINDOW * DD) // 8912896

// ---------------- scratch (device globals; no allocation APIs) ----------------
// g_q is pre-scaled by 0.25 * log2(e) so attention probs = exp2(q'.k)
__device__ float    g_q[(size_t)BB * SS * HD];        // 33.5 MB, layout (b,s,h*d)
__device__ float    g_ao[(size_t)BB * SS * HD];       // 33.5 MB, layout (b,s,h*d)
__device__ unsigned g_wq[4][32 * 128];                // packed ternary weights (q,k,v,o)
__device__ float    g_ws[4];                          // w_scale per weight
__device__ unsigned g_amax_x;
__device__ unsigned g_amax_o;

#define QSCALE 0.3606737602222409f  /* 0.25 * log2(e) */

// ---------------- f32x2 packed-math helpers (sm_103a) ----------------
__device__ __forceinline__ unsigned long long f2_mul(unsigned long long a, unsigned long long b) {
    unsigned long long d;
    asm("mul.rn.f32x2 %0,%1,%2;" : "=l"(d) : "l"(a), "l"(b));
    return d;
}
__device__ __forceinline__ unsigned long long f2_fma(unsigned long long a, unsigned long long b,
                                                     unsigned long long c) {
    unsigned long long d;
    asm("fma.rn.f32x2 %0,%1,%2,%3;" : "=l"(d) : "l"(a), "l"(b), "l"(c));
    return d;
}
__device__ __forceinline__ unsigned long long f2_add(unsigned long long a, unsigned long long b) {
    unsigned long long d;
    asm("add.rn.f32x2 %0,%1,%2;" : "=l"(d) : "l"(a), "l"(b));
    return d;
}
__device__ __forceinline__ unsigned long long f2_pack(float lo, float hi) {
    unsigned long long d;
    asm("mov.b64 %0,{%1,%2};" : "=l"(d) : "f"(lo), "f"(hi));
    return d;
}
__device__ __forceinline__ float2 f2_unpack(unsigned long long v) {
    float2 r;
    asm("mov.b64 {%0,%1},%2;" : "=f"(r.x), "=f"(r.y) : "l"(v));
    return r;
}
__device__ __forceinline__ float fast_ex2(float x) {
    float r;
    asm("ex2.approx.ftz.f32 %0,%1;" : "=f"(r) : "f"(x));
    return r;
}

// ---------------- helpers ----------------
__device__ __forceinline__ unsigned quant4(float4 v, float is_inv) {
    int a = __float2int_rn(fminf(fmaxf(v.x * is_inv, -128.f), 127.f));
    int b = __float2int_rn(fminf(fmaxf(v.y * is_inv, -128.f), 127.f));
    int c = __float2int_rn(fminf(fmaxf(v.z * is_inv, -128.f), 127.f));
    int d = __float2int_rn(fminf(fmaxf(v.w * is_inv, -128.f), 127.f));
    return (unsigned)(a & 0xFF) | ((unsigned)(b & 0xFF) << 8) |
           ((unsigned)(c & 0xFF) << 16) | ((unsigned)(d & 0xFF) << 24);
}

// ---------------- kernel 1: w_scale + ternarize + pack (4 blocks) + init -----
__global__ __launch_bounds__(256) void k_prep(const float* qw, const float* kw,
                                              const float* vw, const float* ow) {
    int bw = blockIdx.x;
    if (bw == 0 && threadIdx.x == 0) { g_amax_x = 0u; g_amax_o = 0u; }
    const float* w = (bw == 0) ? qw : (bw == 1) ? kw : (bw == 2) ? vw : ow;
    __shared__ float red[256];
    __shared__ float ws_s;
    int t = threadIdx.x;
    float s = 0.f;
    for (int i = t; i < 16384; i += 256) s += fabsf(w[i]);
    red[t] = s;
    __syncthreads();
    for (int o = 128; o > 0; o >>= 1) {
        if (t < o) red[t] += red[t + o];
        __syncthreads();
    }
    if (t == 0) { ws_s = red[0] / 16384.0f; g_ws[bw] = ws_s; }
    __syncthreads();
    float thr = 0.5f * ws_s;
    int c = t >> 1, half = t & 1;
    for (int i = 0; i < 16; i++) {
        int kk = half * 16 + i;
        float4 wv = *(const float4*)(w + c * 128 + kk * 4);
        int t0 = (fabsf(wv.x) > thr) ? (wv.x > 0.f ? 1 : -1) : 0;
        int t1 = (fabsf(wv.y) > thr) ? (wv.y > 0.f ? 1 : -1) : 0;
        int t2 = (fabsf(wv.z) > thr) ? (wv.z > 0.f ? 1 : -1) : 0;
        int t3 = (fabsf(wv.w) > thr) ? (wv.w > 0.f ? 1 : -1) : 0;
        unsigned p = (unsigned)(t0 & 0xFF) | ((unsigned)(t1 & 0xFF) << 8) |
                     ((unsigned)(t2 & 0xFF) << 16) | ((unsigned)(t3 & 0xFF) << 24);
        g_wq[bw][kk * 128 + c] = p;
    }
}

// ---------------- kernel 2: abs-max over x ----------------
__global__ __launch_bounds__(256) void k_amax(const float* x, int n4) {
    int idx = blockIdx.x * blockDim.x + threadIdx.x;
    int stride = gridDim.x * blockDim.x;
    float m = 0.f;
    const float4* x4 = (const float4*)x;
    for (int i = idx; i < n4; i += stride) {
        float4 v = x4[i];
        m = fmaxf(m, fmaxf(fmaxf(fabsf(v.x), fabsf(v.y)), fmaxf(fabsf(v.z), fabsf(v.w))));
    }
    for (int o = 16; o; o >>= 1) m = fmaxf(m, __shfl_xor_sync(0xFFFFFFFFu, m, o));
    if ((threadIdx.x & 31) == 0) atomicMax(&g_amax_x, __float_as_uint(m));
}

// ---------------- shared GEMM core: 32 rows x 128 cols, dp4a ----------------
// 256 threads. warp w owns rows 4w..4w+3; lane owns cols 4*lane..4*lane+3
#define DP(a, b, c) c = __dp4a((int)(a), (int)(b), c)

__device__ __forceinline__ void bitgemm_core(const float* xbase, const unsigned* wq_g,
                                             float is_inv, unsigned* xq_s, unsigned* wq_s,
                                             int (&acc)[4][4]) {
    int t = threadIdx.x;
    {
        int row = t >> 3, seg = t & 7;
        const float4* src = (const float4*)(xbase + row * 128 + seg * 16);
        uint4 pk;
        pk.x = quant4(src[0], is_inv);
        pk.y = quant4(src[1], is_inv);
        pk.z = quant4(src[2], is_inv);
        pk.w = quant4(src[3], is_inv);
        *(uint4*)(xq_s + row * 32 + seg * 4) = pk;
    }
    {
        const uint4* src = (const uint4*)wq_g;
        uint4* dst = (uint4*)wq_s;
#pragma unroll
        for (int i = 0; i < 4; i++) dst[t + i * 256] = src[t + i * 256];
    }
    __syncthreads();
    int warp = t >> 5, lane = t & 31;
#pragma unroll
    for (int rr = 0; rr < 4; rr++)
#pragma unroll
        for (int cc = 0; cc < 4; cc++) acc[rr][cc] = 0;
    const uint4* x4 = (const uint4*)xq_s;  // [row*8 + kk/4]
    const uint4* w4 = (const uint4*)wq_s;  // [kk*32 + lane] = cols 4l..4l+3 at word kk
#pragma unroll
    for (int kk = 0; kk < 32; kk += 4) {
        uint4 xr0 = x4[(warp * 4 + 0) * 8 + (kk >> 2)];
        uint4 xr1 = x4[(warp * 4 + 1) * 8 + (kk >> 2)];
        uint4 xr2 = x4[(warp * 4 + 2) * 8 + (kk >> 2)];
        uint4 xr3 = x4[(warp * 4 + 3) * 8 + (kk >> 2)];
        uint4 w0 = w4[(kk + 0) * 32 + lane];
        uint4 w1 = w4[(kk + 1) * 32 + lane];
        uint4 w2 = w4[(kk + 2) * 32 + lane];
        uint4 w3 = w4[(kk + 3) * 32 + lane];
        DP(xr0.x, w0.x, acc[0][0]); DP(xr0.y, w1.x, acc[0][0]); DP(xr0.z, w2.x, acc[0][0]); DP(xr0.w, w3.x, acc[0][0]);
        DP(xr0.x, w0.y, acc[0][1]); DP(xr0.y, w1.y, acc[0][1]); DP(xr0.z, w2.y, acc[0][1]); DP(xr0.w, w3.y, acc[0][1]);
        DP(xr0.x, w0.z, acc[0][2]); DP(xr0.y, w1.z, acc[0][2]); DP(xr0.z, w2.z, acc[0][2]); DP(xr0.w, w3.z, acc[0][2]);
        DP(xr0.x, w0.w, acc[0][3]); DP(xr0.y, w1.w, acc[0][3]); DP(xr0.z, w2.w, acc[0][3]); DP(xr0.w, w3.w, acc[0][3]);
        DP(xr1.x, w0.x, acc[1][0]); DP(xr1.y, w1.x, acc[1][0]); DP(xr1.z, w2.x, acc[1][0]); DP(xr1.w, w3.x, acc[1][0]);
        DP(xr1.x, w0.y, acc[1][1]); DP(xr1.y, w1.y, acc[1][1]); DP(xr1.z, w2.y, acc[1][1]); DP(xr1.w, w3.y, acc[1][1]);
        DP(xr1.x, w0.z, acc[1][2]); DP(xr1.y, w1.z, acc[1][2]); DP(xr1.z, w2.z, acc[1][2]); DP(xr1.w, w3.z, acc[1][2]);
        DP(xr1.x, w0.w, acc[1][3]); DP(xr1.y, w1.w, acc[1][3]); DP(xr1.z, w2.w, acc[1][3]); DP(xr1.w, w3.w, acc[1][3]);
        DP(xr2.x, w0.x, acc[2][0]); DP(xr2.y, w1.x, acc[2][0]); DP(xr2.z, w2.x, acc[2][0]); DP(xr2.w, w3.x, acc[2][0]);
        DP(xr2.x, w0.y, acc[2][1]); DP(xr2.y, w1.y, acc[2][1]); DP(xr2.z, w2.y, acc[2][1]); DP(xr2.w, w3.y, acc[2][1]);
        DP(xr2.x, w0.z, acc[2][2]); DP(xr2.y, w1.z, acc[2][2]); DP(xr2.z, w2.z, acc[2][2]); DP(xr2.w, w3.z, acc[2][2]);
        DP(xr2.x, w0.w, acc[2][3]); DP(xr2.y, w1.w, acc[2][3]); DP(xr2.z, w2.w, acc[2][3]); DP(xr2.w, w3.w, acc[2][3]);
        DP(xr3.x, w0.x, acc[3][0]); DP(xr3.y, w1.x, acc[3][0]); DP(xr3.z, w2.x, acc[3][0]); DP(xr3.w, w3.x, acc[3][0]);
        DP(xr3.x, w0.y, acc[3][1]); DP(xr3.y, w1.y, acc[3][1]); DP(xr3.z, w2.y, acc[3][1]); DP(xr3.w, w3.y, acc[3][1]);
        DP(xr3.x, w0.z, acc[3][2]); DP(xr3.y, w1.z, acc[3][2]); DP(xr3.z, w2.z, acc[3][2]); DP(xr3.w, w3.z, acc[3][2]);
        DP(xr3.x, w0.w, acc[3][3]); DP(xr3.y, w1.w, acc[3][3]); DP(xr3.z, w2.w, acc[3][3]); DP(xr3.w, w3.w, acc[3][3]);
    }
}

// ---------------- kernel 3: Q + K/V projections in one launch ----------------
// blocks [0, 2048): Q rows; [2048, 2176): K rows; [2176, 2304): V rows
__global__ __launch_bounds__(256) void k_proj(const float* x, const float* qb,
                                              const float* kb, const float* vb,
                                              float* out) {
    __shared__ unsigned xq_s[32 * 32];
    __shared__ unsigned wq_s[32 * 128];
    int blk = blockIdx.x;
    float amax = __uint_as_float(g_amax_x);
    float is_inv = __fdiv_rn(127.0f, amax);
    float is = amax * (1.0f / 127.0f);
    int warp = threadIdx.x >> 5, lane = threadIdx.x & 31;
    int c0 = lane * 4;
    int acc[4][4];

    if (blk < 2048) {  // ---- Q ---- (pre-scaled by 0.25*log2e for exp2-domain attn)
        int row0 = blk * 32;
        float sc = g_ws[0] * is;
        bitgemm_core(x + (size_t)row0 * 128, g_wq[0], is_inv, xq_s, wq_s, acc);
        float4 bias = *(const float4*)(qb + c0);
#pragma unroll
        for (int rr = 0; rr < 4; rr++) {
            int r = row0 + warp * 4 + rr;
            float4 o;
            o.x = ((float)acc[rr][0] * sc + bias.x) * QSCALE;
            o.y = ((float)acc[rr][1] * sc + bias.y) * QSCALE;
            o.z = ((float)acc[rr][2] * sc + bias.z) * QSCALE;
            o.w = ((float)acc[rr][3] * sc + bias.w) * QSCALE;
            *(float4*)(g_q + (size_t)r * 128 + c0) = o;
        }
    } else {  // ---- K or V, last 128 tokens of each batch ----
        int which = (blk >= 2176) ? 1 : 0;
        int row0 = (blk - (which ? 2176 : 2048)) * 32;  // r in [0,4096)
        int b = row0 >> 7, i0 = row0 & 127;
        const float* xbase = x + (((size_t)b * SS) + (SS - WINDOW) + i0) * EE;
        float sc = g_ws[1 + which] * is;
        const float* bias_p = which ? vb : kb;
        size_t base = which ? (size_t)VOFF : (size_t)KOFF;
        bitgemm_core(xbase, g_wq[1 + which], is_inv, xq_s, wq_s, acc);
        float4 bias = *(const float4*)(bias_p + c0);
        int h = c0 >> 4, d0 = c0 & 15;
#pragma unroll
        for (int rr = 0; rr < 4; rr++) {
            int r = row0 + warp * 4 + rr;
            int b2 = r >> 7, ii = r & 127;
            float4 o;
            o.x = (float)acc[rr][0] * sc + bias.x;
            o.y = (float)acc[rr][1] * sc + bias.y;
            o.z = (float)acc[rr][2] * sc + bias.z;
            o.w = (float)acc[rr][3] * sc + bias.w;
            *(float4*)(out + base + (((size_t)(b2 * HH + h)) * WINDOW + ii) * DD + d0) = o;
        }
    }
}

// ---------------- attention inner machinery (no-max softmax, exp2 domain) ----
#define NEG_INF __int_as_float(0xff800000)

struct AttState {
    unsigned long long q[8];
    unsigned long long a[8];
    float l;
};

__device__ __forceinline__ void att_load_q(AttState& st, const float* qptr) {
    const ulonglong2* qp = (const ulonglong2*)qptr;
    ulonglong2 q01 = qp[0], q23 = qp[1], q45 = qp[2], q67 = qp[3];
    st.q[0] = q01.x; st.q[1] = q01.y; st.q[2] = q23.x; st.q[3] = q23.y;
    st.q[4] = q45.x; st.q[5] = q45.y; st.q[6] = q67.x; st.q[7] = q67.y;
#pragma unroll
    for (int i = 0; i < 8; i++) st.a[i] = 0ull;
    st.l = 0.f;
}

__device__ __forceinline__ float att_score(const AttState& st,
                                           const ulonglong2& kA, const ulonglong2& kB,
                                           const ulonglong2& kC, const ulonglong2& kD) {
    unsigned long long d0 = f2_mul(st.q[0], kA.x);
    unsigned long long d1 = f2_mul(st.q[1], kA.y);
    d0 = f2_fma(st.q[2], kB.x, d0);
    d1 = f2_fma(st.q[3], kB.y, d1);
    d0 = f2_fma(st.q[4], kC.x, d0);
    d1 = f2_fma(st.q[5], kC.y, d1);
    d0 = f2_fma(st.q[6], kD.x, d0);
    d1 = f2_fma(st.q[7], kD.y, d1);
    float2 ds = f2_unpack(f2_add(d0, d1));
    return ds.x + ds.y;  // log2-domain score (q pre-scaled by 0.25*log2e)
}

__device__ __forceinline__ void att_update(AttState& st, float sc,
                                           const ulonglong2& vA, const ulonglong2& vB,
                                           const ulonglong2& vC, const ulonglong2& vD) {
    float p = fast_ex2(sc);  // scores bounded ~|12|; no overflow possible
    unsigned long long p2 = f2_pack(p, p);
    st.l += p;
    st.a[0] = f2_fma(p2, vA.x, st.a[0]);
    st.a[1] = f2_fma(p2, vA.y, st.a[1]);
    st.a[2] = f2_fma(p2, vB.x, st.a[2]);
    st.a[3] = f2_fma(p2, vB.y, st.a[3]);
    st.a[4] = f2_fma(p2, vC.x, st.a[4]);
    st.a[5] = f2_fma(p2, vC.y, st.a[5]);
    st.a[6] = f2_fma(p2, vD.x, st.a[6]);
    st.a[7] = f2_fma(p2, vD.y, st.a[7]);
}

__device__ __forceinline__ float att_finish(AttState& st, float* optr) {
    float inv = 1.0f / st.l;
    unsigned long long inv2 = f2_pack(inv, inv);
    float mx = 0.f;
#pragma unroll
    for (int i = 0; i < 8; i++) {
        st.a[i] = f2_mul(st.a[i], inv2);
        float2 u = f2_unpack(st.a[i]);
        mx = fmaxf(mx, fmaxf(fabsf(u.x), fabsf(u.y)));
    }
    ulonglong2* op = (ulonglong2*)optr;
    op[0] = make_ulonglong2(st.a[0], st.a[1]);
    op[1] = make_ulonglong2(st.a[2], st.a[3]);
    op[2] = make_ulonglong2(st.a[4], st.a[5]);
    op[3] = make_ulonglong2(st.a[6], st.a[7]);
    return mx;
}

// ---------------- kernel 5: attention, 2 queries/thread, f32x2, branch-free --
// grid: (SS/512, H, B), 256 threads. Thread t handles queries chunk*512+t and +256.
__global__ __launch_bounds__(256, 2) void k_attn(const float* cached_k, const float* cached_v,
                                                 const float* outbuf) {
    __shared__ __align__(16) float ks[KTOT * DD];
    __shared__ __align__(16) float vs[KTOT * DD];
    int b = blockIdx.z, h = blockIdx.y, chunk = blockIdx.x;
    int t = threadIdx.x;
    size_t bh = (size_t)(b * HH + h);
    {
        const float* knew = outbuf + KOFF + bh * WINDOW * DD;
        const float* vnew = outbuf + VOFF + bh * WINDOW * DD;
        const float* kc = cached_k + bh * CACHE * DD;
        const float* vc = cached_v + bh * CACHE * DD;
        for (int i = t; i < KTOT * DD; i += 256) {
            int j = i >> 4;
            ks[i] = (j < SINKS) ? kc[i] : knew[i - SINKS * DD];
            vs[i] = (j < SINKS) ? vc[i] : vnew[i - SINKS * DD];
        }
    }
    __syncthreads();

    int s0 = chunk * 512 + t;
    int s1 = s0 + 256;
    const float* qbase = g_q + ((size_t)b * SS) * HD + h * DD;
    AttState st0, st1;
    att_load_q(st0, qbase + (size_t)s0 * HD);
    att_load_q(st1, qbase + (size_t)s1 * HD);

    const ulonglong2* k2 = (const ulonglong2*)ks;
    const ulonglong2* v2 = (const ulonglong2*)vs;

    if (chunk != 0) {
        // full: both queries attend to all 132 keys
#pragma unroll 2
        for (int j = 0; j < KTOT; j++) {
            ulonglong2 kA = k2[j * 4 + 0], kB = k2[j * 4 + 1];
            ulonglong2 kC = k2[j * 4 + 2], kD = k2[j * 4 + 3];
            float sc0 = att_score(st0, kA, kB, kC, kD);
            float sc1 = att_score(st1, kA, kB, kC, kD);
            ulonglong2 vA = v2[j * 4 + 0], vB = v2[j * 4 + 1];
            ulonglong2 vC = v2[j * 4 + 2], vD = v2[j * 4 + 3];
            att_update(st0, sc0, vA, vB, vC, vD);
            att_update(st1, sc1, vA, vB, vC, vD);
        }
    } else {
        // chunk 0: query s0 = t in [0,255] may be causal-ragged; s1 >= 256 is full
        int jmax0 = min(s0, KTOT - 1);
        for (int j = 0; j < KTOT; j++) {
            ulonglong2 kA = k2[j * 4 + 0], kB = k2[j * 4 + 1];
            ulonglong2 kC = k2[j * 4 + 2], kD = k2[j * 4 + 3];
            float sc0 = att_score(st0, kA, kB, kC, kD);
            float sc1 = att_score(st1, kA, kB, kC, kD);
            sc0 = (j <= jmax0) ? sc0 : NEG_INF;  // ex2(-inf) = 0 contribution
            ulonglong2 vA = v2[j * 4 + 0], vB = v2[j * 4 + 1];
            ulonglong2 vC = v2[j * 4 + 2], vD = v2[j * 4 + 3];
            att_update(st0, sc0, vA, vB, vC, vD);
            att_update(st1, sc1, vA, vB, vC, vD);
        }
    }

    float* aob = g_ao + ((size_t)b * SS) * HD + h * DD;
    float mx0 = att_finish(st0, aob + (size_t)s0 * HD);
    float mx1 = att_finish(st1, aob + (size_t)s1 * HD);
    float mx = fmaxf(mx0, mx1);
    for (int o = 16; o; o >>= 1) mx = fmaxf(mx, __shfl_xor_sync(0xFFFFFFFFu, mx, o));
    if ((t & 31) == 0) atomicMax(&g_amax_o, __float_as_uint(mx));
}

// ---------------- kernel 6: O projection ----------------
__global__ __launch_bounds__(256) void k_oproj(const float* ob, float* out) {
    __shared__ unsigned xq_s[32 * 32];
    __shared__ unsigned wq_s[32 * 128];
    int row0 = blockIdx.x * 32;
    float amax = __uint_as_float(g_amax_o);
    float is_inv = __fdiv_rn(127.0f, amax);
    float sc = g_ws[3] * (amax * (1.0f / 127.0f));
    int acc[4][4];
    bitgemm_core(g_ao + (size_t)row0 * 128, g_wq[3], is_inv, xq_s, wq_s, acc);
    int warp = threadIdx.x >> 5, lane = threadIdx.x & 31;
    int c0 = lane * 4;
    float4 bias = *(const float4*)(ob + c0);
#pragma unroll
    for (int rr = 0; rr < 4; rr++) {
        int r = row0 + warp * 4 + rr;
        float4 o;
        o.x = (float)acc[rr][0] * sc + bias.x;
        o.y = (float)acc[rr][1] * sc + bias.y;
        o.z = (float)acc[rr][2] * sc + bias.z;
        o.w = (float)acc[rr][3] * sc + bias.w;
        *(float4*)(out + (size_t)r * 128 + c0) = o;
    }
}

// ---------------- launcher ----------------
extern "C" void kernel_launch(void* const* d_in, const int* in_sizes, int n_in,
                              void* d_out, int out_size) {
    const float* x  = (const float*)d_in[0];
    const float* ck = (const float*)d_in[1];
    const float* cv = (const float*)d_in[2];
    const float* qb = (const float*)d_in[4];
    const float* kb = (const float*)d_in[6];
    const float* vb = (const float*)d_in[8];
    const float* ob = (const float*)d_in[10];
    const float* qw = (const float*)d_in[3];
    const float* kw = (const float*)d_in[5];
    const float* vw = (const float*)d_in[7];
    const float* ow = (const float*)d_in[9];
    float* out = (float*)d_out;

    k_prep<<<4, 256>>>(qw, kw, vw, ow);
    k_amax<<<1024, 256>>>(x, (BB * SS * EE) / 4);
    k_proj<<<2048 + 256, 256>>>(x, qb, kb, vb, out);
    k_attn<<<dim3(SS / 512, HH, BB), 256>>>(ck, cv, out);
    k_oproj<<<(BB * SS) / 32, 256>>>(ob, out);
}